// round 3
// baseline (speedup 1.0000x reference)
#include <cuda_runtime.h>
#include <math.h>

#define D_MODEL 2048
#define F_DIM   8192
#define NROWS   4096   // B*S
#define NHEAD   16
#define HD      128
#define SEQ     2048

// ---------------- scratch (device globals; no allocations allowed) ----------
__device__ float g_xn [NROWS * D_MODEL];   // normed activations (reused)
__device__ float g_q  [NROWS * D_MODEL];
__device__ float g_k  [NROWS * D_MODEL];
__device__ float g_v  [NROWS * D_MODEL];
__device__ float g_ao [NROWS * D_MODEL];   // attention output (pre-Wo)
__device__ float g_h  [NROWS * D_MODEL];   // residual after attention
__device__ float g_ml [NROWS * F_DIM];     // MLP hidden (post-GELU)

// ---------------- hypersphere norm: x/(||x||+eps)*sqrt(D)*g ------------------
__global__ void hnorm_kernel(const float* __restrict__ x,
                             const float* __restrict__ g,
                             float* __restrict__ out) {
    int row = blockIdx.x;
    int tid = threadIdx.x;
    const float4* xr = (const float4*)(x + (size_t)row * D_MODEL);
    float4 v0 = xr[tid];
    float4 v1 = xr[tid + 256];
    float ss = v0.x*v0.x + v0.y*v0.y + v0.z*v0.z + v0.w*v0.w
             + v1.x*v1.x + v1.y*v1.y + v1.z*v1.z + v1.w*v1.w;
    #pragma unroll
    for (int o = 16; o > 0; o >>= 1) ss += __shfl_xor_sync(0xffffffffu, ss, o);
    __shared__ float red[8];
    if ((tid & 31) == 0) red[tid >> 5] = ss;
    __syncthreads();
    float tot = red[0]+red[1]+red[2]+red[3]+red[4]+red[5]+red[6]+red[7];
    float scale = 45.254833995939045f / (sqrtf(tot) + 1e-6f);  // sqrt(2048)
    const float4* gg = (const float4*)g;
    float4 g0 = gg[tid], g1 = gg[tid + 256];
    float4* orow = (float4*)(out + (size_t)row * D_MODEL);
    float4 o0, o1;
    o0.x = v0.x*scale*g0.x; o0.y = v0.y*scale*g0.y; o0.z = v0.z*scale*g0.z; o0.w = v0.w*scale*g0.w;
    o1.x = v1.x*scale*g1.x; o1.y = v1.y*scale*g1.y; o1.z = v1.z*scale*g1.z; o1.w = v1.w*scale*g1.w;
    orow[tid] = o0;
    orow[tid + 256] = o1;
}

// ---------------- per-head QK norm (one warp per 128-d vector) ---------------
// layout [row, h*128+d] is head-contiguous, so vector index = row*16 + h.
__global__ void qknorm_kernel(float* __restrict__ t, const float* __restrict__ fac) {
    int vec  = blockIdx.x * 8 + (threadIdx.x >> 5);
    int lane = threadIdx.x & 31;
    float4* p = (float4*)(t + (size_t)vec * HD);
    float4 v = p[lane];
    float ss = v.x*v.x + v.y*v.y + v.z*v.z + v.w*v.w;
    #pragma unroll
    for (int o = 16; o > 0; o >>= 1) ss += __shfl_xor_sync(0xffffffffu, ss, o);
    float f = fac ? fac[0] : 1.0f;
    float s = f / (sqrtf(ss) + 1e-6f);
    v.x *= s; v.y *= s; v.z *= s; v.w *= s;
    p[lane] = v;
}

// ---------------- tiled fp32 NT-GEMM: C[M,N] = A[M,K] * B[N,K]^T (+R, gelu) --
#define BM 128
#define BN 128
#define BK 16

__device__ __forceinline__ float gelu_exact(float x) {
    return 0.5f * x * (1.0f + erff(x * 0.70710678118654752f));
}

template<int EPI>   // 0 = none, 1 = GELU
__global__ __launch_bounds__(256, 2)
void gemm_nt_kernel(const float* __restrict__ A, const float* __restrict__ B,
                    float* __restrict__ C, const float* __restrict__ R,
                    int M, int N, int K) {
    __shared__ float As[BK][BM + 4];
    __shared__ float Bs[BK][BN + 4];
    int tid = threadIdx.x;
    int m0 = blockIdx.y * BM, n0 = blockIdx.x * BN;
    int tx = tid & 15, ty = tid >> 4;

    float acc[8][8];
    #pragma unroll
    for (int i = 0; i < 8; i++)
        #pragma unroll
        for (int j = 0; j < 8; j++) acc[i][j] = 0.f;

    for (int k0 = 0; k0 < K; k0 += BK) {
        #pragma unroll
        for (int i = 0; i < 2; i++) {
            int f = tid + i * 256;        // float4 index, 512 total
            int r = f >> 2;               // 0..127
            int c = (f & 3) << 2;         // 0,4,8,12
            float4 va = *(const float4*)(A + (size_t)(m0 + r) * K + k0 + c);
            As[c + 0][r] = va.x; As[c + 1][r] = va.y;
            As[c + 2][r] = va.z; As[c + 3][r] = va.w;
            float4 vb = *(const float4*)(B + (size_t)(n0 + r) * K + k0 + c);
            Bs[c + 0][r] = vb.x; Bs[c + 1][r] = vb.y;
            Bs[c + 2][r] = vb.z; Bs[c + 3][r] = vb.w;
        }
        __syncthreads();
        #pragma unroll
        for (int kk = 0; kk < BK; kk++) {
            float a[8], b[8];
            #pragma unroll
            for (int i = 0; i < 8; i++) a[i] = As[kk][ty * 8 + i];
            #pragma unroll
            for (int j = 0; j < 8; j++) b[j] = Bs[kk][tx * 8 + j];
            #pragma unroll
            for (int i = 0; i < 8; i++)
                #pragma unroll
                for (int j = 0; j < 8; j++) acc[i][j] = fmaf(a[i], b[j], acc[i][j]);
        }
        __syncthreads();
    }

    #pragma unroll
    for (int i = 0; i < 8; i++) {
        int r = m0 + ty * 8 + i;
        #pragma unroll
        for (int j = 0; j < 8; j++) {
            int c = n0 + tx * 8 + j;
            float v = acc[i][j];
            if (R) v += R[(size_t)r * N + c];
            if (EPI == 1) v = gelu_exact(v);
            C[(size_t)r * N + c] = v;
        }
    }
}

// ---------------- causal flash attention (fp32, 64x64 tiles, hd=128) ---------
#define FB 64
#define KS_STRIDE 68   // padded transposed-K stride (keeps 16B alignment)

__global__ __launch_bounds__(256, 1)
void flash_kernel(const float* __restrict__ Q, const float* __restrict__ Kg,
                  const float* __restrict__ V, float* __restrict__ O) {
    extern __shared__ float sm[];
    float* Qs = sm;                          // [64][128]
    float* Ks = Qs + FB * HD;                // [128][KS_STRIDE] transposed
    float* Vs = Ks + HD * KS_STRIDE;         // [64][128]
    float* Ss = Vs + FB * HD;                // [64][64]

    int qt = blockIdx.x, h = blockIdx.y, b = blockIdx.z;
    int tid = threadIdx.x;
    int w = tid >> 5, lane = tid & 31;
    int tx = tid & 15, ty = tid >> 4;
    size_t base = (size_t)b * SEQ * D_MODEL + (size_t)h * HD;
    int q0 = qt * FB;

    // load Q tile
    #pragma unroll
    for (int i = 0; i < 8; i++) {
        int f = tid + i * 256;
        int r = f >> 5;
        int d = (f & 31) << 2;
        *(float4*)&Qs[r * HD + d] =
            *(const float4*)(Q + base + (size_t)(q0 + r) * D_MODEL + d);
    }

    float m[8], l[8], oc[8][4];
    #pragma unroll
    for (int i = 0; i < 8; i++) {
        m[i] = -INFINITY; l[i] = 0.f;
        oc[i][0] = oc[i][1] = oc[i][2] = oc[i][3] = 0.f;
    }
    __syncthreads();

    for (int j0 = 0; j0 <= qt; j0++) {
        int k0 = j0 * FB;
        __syncthreads();   // previous phase-C readers done before overwriting K/V
        #pragma unroll
        for (int i = 0; i < 8; i++) {
            int f = tid + i * 256;
            int r = f >> 5;
            int d = (f & 31) << 2;
            float4 kv = *(const float4*)(Kg + base + (size_t)(k0 + r) * D_MODEL + d);
            Ks[(d + 0) * KS_STRIDE + r] = kv.x;
            Ks[(d + 1) * KS_STRIDE + r] = kv.y;
            Ks[(d + 2) * KS_STRIDE + r] = kv.z;
            Ks[(d + 3) * KS_STRIDE + r] = kv.w;
            *(float4*)&Vs[r * HD + d] =
                *(const float4*)(V + base + (size_t)(k0 + r) * D_MODEL + d);
        }
        __syncthreads();

        // Phase A: S = Q*K^T (4x4 per thread, 16x16 grid)
        float s[4][4];
        #pragma unroll
        for (int i = 0; i < 4; i++)
            #pragma unroll
            for (int j = 0; j < 4; j++) s[i][j] = 0.f;
        #pragma unroll 4
        for (int kk = 0; kk < HD; kk++) {
            float4 b4 = *(const float4*)&Ks[kk * KS_STRIDE + tx * 4];
            #pragma unroll
            for (int i = 0; i < 4; i++) {
                float a = Qs[(ty * 4 + i) * HD + kk];
                s[i][0] = fmaf(a, b4.x, s[i][0]);
                s[i][1] = fmaf(a, b4.y, s[i][1]);
                s[i][2] = fmaf(a, b4.z, s[i][2]);
                s[i][3] = fmaf(a, b4.w, s[i][3]);
            }
        }
        bool diag = (j0 == qt);
        #pragma unroll
        for (int i = 0; i < 4; i++)
            #pragma unroll
            for (int j = 0; j < 4; j++) {
                float v = s[i][j];
                if (diag && (tx * 4 + j) > (ty * 4 + i)) v = -1e30f;
                Ss[(ty * 4 + i) * FB + tx * 4 + j] = v;
            }
        __syncthreads();

        // Phase B: streaming softmax, per-warp rows w*8..w*8+7
        #pragma unroll
        for (int i = 0; i < 8; i++) {
            int r = w * 8 + i;
            float s0 = Ss[r * FB + lane];
            float s1 = Ss[r * FB + lane + 32];
            float mx = fmaxf(s0, s1);
            #pragma unroll
            for (int o = 16; o > 0; o >>= 1)
                mx = fmaxf(mx, __shfl_xor_sync(0xffffffffu, mx, o));
            float mnew = fmaxf(m[i], mx);
            float p0 = __expf(s0 - mnew);
            float p1 = __expf(s1 - mnew);
            Ss[r * FB + lane] = p0;
            Ss[r * FB + lane + 32] = p1;
            float ls = p0 + p1;
            #pragma unroll
            for (int o = 16; o > 0; o >>= 1)
                ls += __shfl_xor_sync(0xffffffffu, ls, o);
            float corr = __expf(m[i] - mnew);
            l[i] = l[i] * corr + ls;
            m[i] = mnew;
            oc[i][0] *= corr; oc[i][1] *= corr; oc[i][2] *= corr; oc[i][3] *= corr;
        }
        __syncwarp();

        // Phase C: O += P*V
        for (int jj = 0; jj < FB; jj++) {
            float v0 = Vs[jj * HD + lane];
            float v1 = Vs[jj * HD + lane + 32];
            float v2 = Vs[jj * HD + lane + 64];
            float v3 = Vs[jj * HD + lane + 96];
            #pragma unroll
            for (int i = 0; i < 8; i++) {
                float p = Ss[(w * 8 + i) * FB + jj];
                oc[i][0] = fmaf(p, v0, oc[i][0]);
                oc[i][1] = fmaf(p, v1, oc[i][1]);
                oc[i][2] = fmaf(p, v2, oc[i][2]);
                oc[i][3] = fmaf(p, v3, oc[i][3]);
            }
        }
    }

    // epilogue
    #pragma unroll
    for (int i = 0; i < 8; i++) {
        int r = w * 8 + i;
        float inv = 1.0f / l[i];
        float* orow = O + base + (size_t)(q0 + r) * D_MODEL;
        orow[lane]      = oc[i][0] * inv;
        orow[lane + 32] = oc[i][1] * inv;
        orow[lane + 64] = oc[i][2] * inv;
        orow[lane + 96] = oc[i][3] * inv;
    }
}

// ---------------- launch ------------------------------------------------------
extern "C" void kernel_launch(void* const* d_in, const int* in_sizes, int n_in,
                              void* d_out, int out_size) {
    const float* x     = (const float*)d_in[0];
    const float* Wq    = (const float*)d_in[1];
    const float* Wk    = (const float*)d_in[2];
    const float* Wv    = (const float*)d_in[3];
    const float* Wo    = (const float*)d_in[4];
    const float* W_in  = (const float*)d_in[5];
    const float* W_out = (const float*)d_in[6];
    const float* fac   = (const float*)d_in[7];
    const float* gatt  = (const float*)d_in[8];
    const float* gmlp  = (const float*)d_in[9];
    float* out = (float*)d_out;

    float *xn, *q, *k, *v, *ao, *h, *ml;
    cudaGetSymbolAddress((void**)&xn, g_xn);
    cudaGetSymbolAddress((void**)&q,  g_q);
    cudaGetSymbolAddress((void**)&k,  g_k);
    cudaGetSymbolAddress((void**)&v,  g_v);
    cudaGetSymbolAddress((void**)&ao, g_ao);
    cudaGetSymbolAddress((void**)&h,  g_h);
    cudaGetSymbolAddress((void**)&ml, g_ml);

    const int FLASH_SMEM = (FB*HD + HD*KS_STRIDE + FB*HD + FB*FB) * sizeof(float);
    cudaFuncSetAttribute(flash_kernel, cudaFuncAttributeMaxDynamicSharedMemorySize, FLASH_SMEM);

    // 1) pre-attention hypersphere norm
    hnorm_kernel<<<NROWS, 256>>>(x, gatt, xn);

    // 2) QKV projections
    gemm_nt_kernel<0><<<dim3(D_MODEL/BN, NROWS/BM), 256>>>(xn, Wq, q, nullptr, NROWS, D_MODEL, D_MODEL);
    gemm_nt_kernel<0><<<dim3(D_MODEL/BN, NROWS/BM), 256>>>(xn, Wk, k, nullptr, NROWS, D_MODEL, D_MODEL);
    gemm_nt_kernel<0><<<dim3(D_MODEL/BN, NROWS/BM), 256>>>(xn, Wv, v, nullptr, NROWS, D_MODEL, D_MODEL);

    // 3) QK norm (qk_norm_factor folded into q)
    qknorm_kernel<<<NROWS * NHEAD / 8, 256>>>(q, fac);
    qknorm_kernel<<<NROWS * NHEAD / 8, 256>>>(k, nullptr);

    // 4) causal flash attention
    flash_kernel<<<dim3(SEQ/FB, NHEAD, 2), 256, FLASH_SMEM>>>(q, k, v, ao);

    // 5) output projection + residual -> h
    gemm_nt_kernel<0><<<dim3(D_MODEL/BN, NROWS/BM), 256>>>(ao, Wo, h, x, NROWS, D_MODEL, D_MODEL);

    // 6) pre-MLP hypersphere norm (reuse xn)
    hnorm_kernel<<<NROWS, 256>>>(h, gmlp, xn);

    // 7) MLP in + exact GELU
    gemm_nt_kernel<1><<<dim3(F_DIM/BN, NROWS/BM), 256>>>(xn, W_in, ml, nullptr, NROWS, F_DIM, D_MODEL);

    // 8) MLP out + residual -> final output
    gemm_nt_kernel<0><<<dim3(D_MODEL/BN, NROWS/BM), 256>>>(ml, W_out, out, h, NROWS, D_MODEL, F_DIM);
}

// round 8
// speedup vs baseline: 2.5704x; 2.5704x over previous
#include <cuda_runtime.h>
#include <math.h>
#include <stdint.h>

#define D_MODEL 2048
#define F_DIM   8192
#define NROWS   4096   // B*S
#define NHEAD   16
#define HD      128
#define SEQ     2048

// ---------------- scratch (device globals; no allocations allowed) ----------
__device__ float g_xn [NROWS * D_MODEL];
__device__ float g_q  [NROWS * D_MODEL];
__device__ float g_k  [NROWS * D_MODEL];
__device__ float g_v  [NROWS * D_MODEL];
__device__ float g_ao [NROWS * D_MODEL];
__device__ float g_h  [NROWS * D_MODEL];
__device__ float g_ml [NROWS * F_DIM];
// tf32-rounded weights
__device__ float g_wq [D_MODEL * D_MODEL];
__device__ float g_wk [D_MODEL * D_MODEL];
__device__ float g_wv [D_MODEL * D_MODEL];
__device__ float g_wo [D_MODEL * D_MODEL];
__device__ float g_win[F_DIM * D_MODEL];
__device__ float g_wout[D_MODEL * F_DIM];

// ---------------- helpers ----------------------------------------------------
__device__ __forceinline__ float rna_tf32(float x) {
    float r;
    asm("cvt.rna.tf32.f32 %0, %1;" : "=f"(r) : "f"(x));
    return r;
}

__device__ __forceinline__ uint32_t smem_u32(const void* p) {
    uint32_t a;
    asm("{ .reg .u64 t; cvta.to.shared.u64 t, %1; cvt.u32.u64 %0, t; }" : "=r"(a) : "l"(p));
    return a;
}

#define CP_ASYNC16(dst, src) \
    asm volatile("cp.async.cg.shared.global [%0], [%1], 16;" :: "r"(dst), "l"(src) : "memory")
#define CP_COMMIT() asm volatile("cp.async.commit_group;" ::: "memory")
#define CP_WAIT(n)  asm volatile("cp.async.wait_group %0;" :: "n"(n) : "memory")

__device__ __forceinline__ void mma_tf32(float* c, const uint32_t* a, const uint32_t* b) {
    asm volatile(
        "mma.sync.aligned.m16n8k8.row.col.f32.tf32.tf32.f32 "
        "{%0,%1,%2,%3}, {%4,%5,%6,%7}, {%8,%9}, {%0,%1,%2,%3};"
        : "+f"(c[0]), "+f"(c[1]), "+f"(c[2]), "+f"(c[3])
        : "r"(a[0]), "r"(a[1]), "r"(a[2]), "r"(a[3]), "r"(b[0]), "r"(b[1]));
}

__device__ __forceinline__ float gelu_exact(float x) {
    return 0.5f * x * (1.0f + erff(x * 0.70710678118654752f));
}

// ---------------- weight rounding to tf32 (RNA) ------------------------------
__global__ void round4_kernel(const float4* __restrict__ in, float4* __restrict__ out, int n4) {
    int i = blockIdx.x * blockDim.x + threadIdx.x;
    if (i < n4) {
        float4 v = in[i];
        v.x = rna_tf32(v.x); v.y = rna_tf32(v.y);
        v.z = rna_tf32(v.z); v.w = rna_tf32(v.w);
        out[i] = v;
    }
}

// ---------------- hypersphere norm (output rounded to tf32) ------------------
__global__ void hnorm_kernel(const float* __restrict__ x,
                             const float* __restrict__ g,
                             float* __restrict__ out) {
    int row = blockIdx.x;
    int tid = threadIdx.x;
    const float4* xr = (const float4*)(x + (size_t)row * D_MODEL);
    float4 v0 = xr[tid];
    float4 v1 = xr[tid + 256];
    float ss = v0.x*v0.x + v0.y*v0.y + v0.z*v0.z + v0.w*v0.w
             + v1.x*v1.x + v1.y*v1.y + v1.z*v1.z + v1.w*v1.w;
    #pragma unroll
    for (int o = 16; o > 0; o >>= 1) ss += __shfl_xor_sync(0xffffffffu, ss, o);
    __shared__ float red[8];
    if ((tid & 31) == 0) red[tid >> 5] = ss;
    __syncthreads();
    float tot = red[0]+red[1]+red[2]+red[3]+red[4]+red[5]+red[6]+red[7];
    float scale = 45.254833995939045f / (sqrtf(tot) + 1e-6f);
    const float4* gg = (const float4*)g;
    float4 g0 = gg[tid], g1 = gg[tid + 256];
    float4* orow = (float4*)(out + (size_t)row * D_MODEL);
    float4 o0, o1;
    o0.x = rna_tf32(v0.x*scale*g0.x); o0.y = rna_tf32(v0.y*scale*g0.y);
    o0.z = rna_tf32(v0.z*scale*g0.z); o0.w = rna_tf32(v0.w*scale*g0.w);
    o1.x = rna_tf32(v1.x*scale*g1.x); o1.y = rna_tf32(v1.y*scale*g1.y);
    o1.z = rna_tf32(v1.z*scale*g1.z); o1.w = rna_tf32(v1.w*scale*g1.w);
    orow[tid] = o0;
    orow[tid + 256] = o1;
}

// ---------------- per-head QK norm -------------------------------------------
__global__ void qknorm_kernel(float* __restrict__ t, const float* __restrict__ fac) {
    int vec  = blockIdx.x * 8 + (threadIdx.x >> 5);
    int lane = threadIdx.x & 31;
    float4* p = (float4*)(t + (size_t)vec * HD);
    float4 v = p[lane];
    float ss = v.x*v.x + v.y*v.y + v.z*v.z + v.w*v.w;
    #pragma unroll
    for (int o = 16; o > 0; o >>= 1) ss += __shfl_xor_sync(0xffffffffu, ss, o);
    float f = fac ? fac[0] : 1.0f;
    float s = f / (sqrtf(ss) + 1e-6f);
    v.x *= s; v.y *= s; v.z *= s; v.w *= s;
    p[lane] = v;
}

// ---------------- tf32 mma.sync NT-GEMM: C[M,N]=A[M,K]*B[N,K]^T (+R, gelu) ---
// CTA tile 128x128, BK=32, 8 warps (2x4), warp tile 64x32, frags m16n8k8.
// Smem tiles stored [row][36]: stride 36 floats -> conflict-free fragment
// gathers (bank = 4*(lane>>2) + (lane&3)), 144B row stride keeps cp.async
// 16B-aligned.
#define GKT     32
#define TSTR    36
#define STG_FLT (2 * 128 * TSTR)                 // floats per stage (A+B)
#define GEMM_SMEM (2 * STG_FLT * 4)              // 73728 bytes

__device__ __forceinline__ void g_load_stage(uint32_t sbase, int s,
                                             const float* __restrict__ A,
                                             const float* __restrict__ B,
                                             int m0, int n0, int K, int j, int tid) {
    int k0 = j * GKT;
    uint32_t stage = sbase + (uint32_t)s * (STG_FLT * 4);
    #pragma unroll
    for (int t = 0; t < 4; t++) {
        int cid = tid + t * 256;          // 0..1023
        int r = cid >> 3, c = cid & 7;
        uint32_t dst = stage + (uint32_t)(r * TSTR + c * 4) * 4;
        CP_ASYNC16(dst, A + (size_t)(m0 + r) * K + k0 + c * 4);
    }
    #pragma unroll
    for (int t = 0; t < 4; t++) {
        int cid = tid + t * 256;
        int r = cid >> 3, c = cid & 7;
        uint32_t dst = stage + (uint32_t)(128 * TSTR + r * TSTR + c * 4) * 4;
        CP_ASYNC16(dst, B + (size_t)(n0 + r) * K + k0 + c * 4);
    }
}

template<int EPI>   // 0 = none, 1 = GELU + round-to-tf32
__global__ __launch_bounds__(256)
void gemm_mma(const float* __restrict__ A, const float* __restrict__ B,
              float* __restrict__ C, const float* __restrict__ R,
              int N, int K) {
    extern __shared__ float smf[];
    uint32_t sbase = smem_u32(smf);

    int tid = threadIdx.x;
    int wid = tid >> 5, lane = tid & 31;
    int warp_m = wid >> 2, warp_n = wid & 3;     // 2 x 4 warp grid
    int m0 = blockIdx.y * 128, n0 = blockIdx.x * 128;
    int qid = lane >> 2, qtr = lane & 3;

    float acc[4][4][4];
    #pragma unroll
    for (int mi = 0; mi < 4; mi++)
        #pragma unroll
        for (int ni = 0; ni < 4; ni++)
            #pragma unroll
            for (int r = 0; r < 4; r++) acc[mi][ni][r] = 0.f;

    int KT = K / GKT;
    g_load_stage(sbase, 0, A, B, m0, n0, K, 0, tid);
    CP_COMMIT();

    for (int i = 0; i < KT; i++) {
        if (i + 1 < KT) {
            g_load_stage(sbase, (i + 1) & 1, A, B, m0, n0, K, i + 1, tid);
            CP_COMMIT();
            CP_WAIT(1);
        } else {
            CP_WAIT(0);
        }
        __syncthreads();

        const float* As = smf + (i & 1) * STG_FLT;
        const float* Bs = As + 128 * TSTR;
        #pragma unroll
        for (int ks = 0; ks < 4; ks++) {
            int k = ks * 8 + qtr;
            uint32_t af[4][4];
            #pragma unroll
            for (int mi = 0; mi < 4; mi++) {
                const float* p = As + (warp_m * 64 + mi * 16 + qid) * TSTR + k;
                af[mi][0] = __float_as_uint(p[0]);
                af[mi][1] = __float_as_uint(p[8 * TSTR]);
                af[mi][2] = __float_as_uint(p[4]);
                af[mi][3] = __float_as_uint(p[8 * TSTR + 4]);
            }
            uint32_t bf[4][2];
            #pragma unroll
            for (int ni = 0; ni < 4; ni++) {
                const float* p = Bs + (warp_n * 32 + ni * 8 + qid) * TSTR + k;
                bf[ni][0] = __float_as_uint(p[0]);
                bf[ni][1] = __float_as_uint(p[4]);
            }
            #pragma unroll
            for (int mi = 0; mi < 4; mi++)
                #pragma unroll
                for (int ni = 0; ni < 4; ni++)
                    mma_tf32(acc[mi][ni], af[mi], bf[ni]);
        }
        __syncthreads();
    }

    // epilogue: c0/c1 at (row, 2q), c2/c3 at (row+8, 2q)
    #pragma unroll
    for (int mi = 0; mi < 4; mi++) {
        int r1 = m0 + warp_m * 64 + mi * 16 + qid;
        int r2 = r1 + 8;
        #pragma unroll
        for (int ni = 0; ni < 4; ni++) {
            int cc = n0 + warp_n * 32 + ni * 8 + 2 * qtr;
            float2 v0 = make_float2(acc[mi][ni][0], acc[mi][ni][1]);
            float2 v1 = make_float2(acc[mi][ni][2], acc[mi][ni][3]);
            if (R) {
                float2 rv0 = *(const float2*)(R + (size_t)r1 * N + cc);
                float2 rv1 = *(const float2*)(R + (size_t)r2 * N + cc);
                v0.x += rv0.x; v0.y += rv0.y;
                v1.x += rv1.x; v1.y += rv1.y;
            }
            if (EPI == 1) {
                v0.x = rna_tf32(gelu_exact(v0.x));
                v0.y = rna_tf32(gelu_exact(v0.y));
                v1.x = rna_tf32(gelu_exact(v1.x));
                v1.y = rna_tf32(gelu_exact(v1.y));
            }
            *(float2*)(C + (size_t)r1 * N + cc) = v0;
            *(float2*)(C + (size_t)r2 * N + cc) = v1;
        }
    }
}

// ---------------- causal flash attention (fp32, 64x64 tiles, hd=128) ---------
#define FB 64
#define KS_STRIDE 68

__global__ __launch_bounds__(256, 1)
void flash_kernel(const float* __restrict__ Q, const float* __restrict__ Kg,
                  const float* __restrict__ V, float* __restrict__ O) {
    extern __shared__ float smf[];
    float* Qs = smf;
    float* Ks = Qs + FB * HD;
    float* Vs = Ks + HD * KS_STRIDE;
    float* Ss = Vs + FB * HD;

    int qt = blockIdx.x, h = blockIdx.y, b = blockIdx.z;
    int tid = threadIdx.x;
    int w = tid >> 5, lane = tid & 31;
    int tx = tid & 15, ty = tid >> 4;
    size_t base = (size_t)b * SEQ * D_MODEL + (size_t)h * HD;
    int q0 = qt * FB;

    #pragma unroll
    for (int i = 0; i < 8; i++) {
        int f = tid + i * 256;
        int r = f >> 5;
        int d = (f & 31) << 2;
        *(float4*)&Qs[r * HD + d] =
            *(const float4*)(Q + base + (size_t)(q0 + r) * D_MODEL + d);
    }

    float m[8], l[8], oc[8][4];
    #pragma unroll
    for (int i = 0; i < 8; i++) {
        m[i] = -INFINITY; l[i] = 0.f;
        oc[i][0] = oc[i][1] = oc[i][2] = oc[i][3] = 0.f;
    }
    __syncthreads();

    for (int j0 = 0; j0 <= qt; j0++) {
        int k0 = j0 * FB;
        __syncthreads();
        #pragma unroll
        for (int i = 0; i < 8; i++) {
            int f = tid + i * 256;
            int r = f >> 5;
            int d = (f & 31) << 2;
            float4 kv = *(const float4*)(Kg + base + (size_t)(k0 + r) * D_MODEL + d);
            Ks[(d + 0) * KS_STRIDE + r] = kv.x;
            Ks[(d + 1) * KS_STRIDE + r] = kv.y;
            Ks[(d + 2) * KS_STRIDE + r] = kv.z;
            Ks[(d + 3) * KS_STRIDE + r] = kv.w;
            *(float4*)&Vs[r * HD + d] =
                *(const float4*)(V + base + (size_t)(k0 + r) * D_MODEL + d);
        }
        __syncthreads();

        float s[4][4];
        #pragma unroll
        for (int i = 0; i < 4; i++)
            #pragma unroll
            for (int j = 0; j < 4; j++) s[i][j] = 0.f;
        #pragma unroll 4
        for (int kk = 0; kk < HD; kk++) {
            float4 b4 = *(const float4*)&Ks[kk * KS_STRIDE + tx * 4];
            #pragma unroll
            for (int i = 0; i < 4; i++) {
                float a = Qs[(ty * 4 + i) * HD + kk];
                s[i][0] = fmaf(a, b4.x, s[i][0]);
                s[i][1] = fmaf(a, b4.y, s[i][1]);
                s[i][2] = fmaf(a, b4.z, s[i][2]);
                s[i][3] = fmaf(a, b4.w, s[i][3]);
            }
        }
        bool diag = (j0 == qt);
        #pragma unroll
        for (int i = 0; i < 4; i++)
            #pragma unroll
            for (int j = 0; j < 4; j++) {
                float v = s[i][j];
                if (diag && (tx * 4 + j) > (ty * 4 + i)) v = -1e30f;
                Ss[(ty * 4 + i) * FB + tx * 4 + j] = v;
            }
        __syncthreads();

        #pragma unroll
        for (int i = 0; i < 8; i++) {
            int r = w * 8 + i;
            float s0 = Ss[r * FB + lane];
            float s1 = Ss[r * FB + lane + 32];
            float mx = fmaxf(s0, s1);
            #pragma unroll
            for (int o = 16; o > 0; o >>= 1)
                mx = fmaxf(mx, __shfl_xor_sync(0xffffffffu, mx, o));
            float mnew = fmaxf(m[i], mx);
            float p0 = __expf(s0 - mnew);
            float p1 = __expf(s1 - mnew);
            Ss[r * FB + lane] = p0;
            Ss[r * FB + lane + 32] = p1;
            float ls = p0 + p1;
            #pragma unroll
            for (int o = 16; o > 0; o >>= 1)
                ls += __shfl_xor_sync(0xffffffffu, ls, o);
            float corr = __expf(m[i] - mnew);
            l[i] = l[i] * corr + ls;
            m[i] = mnew;
            oc[i][0] *= corr; oc[i][1] *= corr; oc[i][2] *= corr; oc[i][3] *= corr;
        }
        __syncwarp();

        for (int jj = 0; jj < FB; jj++) {
            float v0 = Vs[jj * HD + lane];
            float v1 = Vs[jj * HD + lane + 32];
            float v2 = Vs[jj * HD + lane + 64];
            float v3 = Vs[jj * HD + lane + 96];
            #pragma unroll
            for (int i = 0; i < 8; i++) {
                float p = Ss[(w * 8 + i) * FB + jj];
                oc[i][0] = fmaf(p, v0, oc[i][0]);
                oc[i][1] = fmaf(p, v1, oc[i][1]);
                oc[i][2] = fmaf(p, v2, oc[i][2]);
                oc[i][3] = fmaf(p, v3, oc[i][3]);
            }
        }
    }

    #pragma unroll
    for (int i = 0; i < 8; i++) {
        int r = w * 8 + i;
        float inv = 1.0f / l[i];
        float* orow = O + base + (size_t)(q0 + r) * D_MODEL;
        orow[lane]      = rna_tf32(oc[i][0] * inv);
        orow[lane + 32] = rna_tf32(oc[i][1] * inv);
        orow[lane + 64] = rna_tf32(oc[i][2] * inv);
        orow[lane + 96] = rna_tf32(oc[i][3] * inv);
    }
}

// ---------------- launch ------------------------------------------------------
extern "C" void kernel_launch(void* const* d_in, const int* in_sizes, int n_in,
                              void* d_out, int out_size) {
    const float* x     = (const float*)d_in[0];
    const float* Wq    = (const float*)d_in[1];
    const float* Wk    = (const float*)d_in[2];
    const float* Wv    = (const float*)d_in[3];
    const float* Wo    = (const float*)d_in[4];
    const float* W_in  = (const float*)d_in[5];
    const float* W_out = (const float*)d_in[6];
    const float* fac   = (const float*)d_in[7];
    const float* gatt  = (const float*)d_in[8];
    const float* gmlp  = (const float*)d_in[9];
    float* out = (float*)d_out;

    float *xn, *q, *k, *v, *ao, *h, *ml;
    float *wq, *wk, *wv, *wo, *win, *wout;
    cudaGetSymbolAddress((void**)&xn, g_xn);
    cudaGetSymbolAddress((void**)&q,  g_q);
    cudaGetSymbolAddress((void**)&k,  g_k);
    cudaGetSymbolAddress((void**)&v,  g_v);
    cudaGetSymbolAddress((void**)&ao, g_ao);
    cudaGetSymbolAddress((void**)&h,  g_h);
    cudaGetSymbolAddress((void**)&ml, g_ml);
    cudaGetSymbolAddress((void**)&wq, g_wq);
    cudaGetSymbolAddress((void**)&wk, g_wk);
    cudaGetSymbolAddress((void**)&wv, g_wv);
    cudaGetSymbolAddress((void**)&wo, g_wo);
    cudaGetSymbolAddress((void**)&win,  g_win);
    cudaGetSymbolAddress((void**)&wout, g_wout);

    const int FLASH_SMEM = (FB*HD + HD*KS_STRIDE + FB*HD + FB*FB) * sizeof(float);
    cudaFuncSetAttribute(flash_kernel, cudaFuncAttributeMaxDynamicSharedMemorySize, FLASH_SMEM);
    cudaFuncSetAttribute(gemm_mma<0>, cudaFuncAttributeMaxDynamicSharedMemorySize, GEMM_SMEM);
    cudaFuncSetAttribute(gemm_mma<1>, cudaFuncAttributeMaxDynamicSharedMemorySize, GEMM_SMEM);

    // 0) round weights to tf32 (RNA)
    const int nDD = D_MODEL * D_MODEL / 4;
    const int nFD = F_DIM * D_MODEL / 4;
    round4_kernel<<<(nDD + 255) / 256, 256>>>((const float4*)Wq, (float4*)wq, nDD);
    round4_kernel<<<(nDD + 255) / 256, 256>>>((const float4*)Wk, (float4*)wk, nDD);
    round4_kernel<<<(nDD + 255) / 256, 256>>>((const float4*)Wv, (float4*)wv, nDD);
    round4_kernel<<<(nFD + 255) / 256, 256>>>((const float4*)W_in,  (float4*)win,  nFD);
    round4_kernel<<<(nFD + 255) / 256, 256>>>((const float4*)W_out, (float4*)wout, nFD);
    round4_kernel<<<(nDD + 255) / 256, 256>>>((const float4*)Wo, (float4*)wo, nDD);

    // 1) pre-attention hypersphere norm (tf32-rounded output)
    hnorm_kernel<<<NROWS, 256>>>(x, gatt, xn);

    // 2) QKV projections (tensor-core tf32 mma.sync)
    dim3 gDD(D_MODEL / 128, NROWS / 128);
    gemm_mma<0><<<gDD, 256, GEMM_SMEM>>>(xn, wq, q, nullptr, D_MODEL, D_MODEL);
    gemm_mma<0><<<gDD, 256, GEMM_SMEM>>>(xn, wk, k, nullptr, D_MODEL, D_MODEL);
    gemm_mma<0><<<gDD, 256, GEMM_SMEM>>>(xn, wv, v, nullptr, D_MODEL, D_MODEL);

    // 3) QK norm (factor folded into q)
    qknorm_kernel<<<NROWS * NHEAD / 8, 256>>>(q, fac);
    qknorm_kernel<<<NROWS * NHEAD / 8, 256>>>(k, nullptr);

    // 4) causal flash attention (fp32; output rounded to tf32 for Wo GEMM)
    flash_kernel<<<dim3(SEQ/FB, NHEAD, 2), 256, FLASH_SMEM>>>(q, k, v, ao);

    // 5) output projection + residual
    gemm_mma<0><<<gDD, 256, GEMM_SMEM>>>(ao, wo, h, x, D_MODEL, D_MODEL);

    // 6) pre-MLP hypersphere norm
    hnorm_kernel<<<NROWS, 256>>>(h, gmlp, xn);

    // 7) MLP in + GELU (+ tf32 round for next GEMM's A)
    gemm_mma<1><<<dim3(F_DIM / 128, NROWS / 128), 256, GEMM_SMEM>>>(xn, win, ml, nullptr, F_DIM, D_MODEL);

    // 8) MLP out + residual -> final
    gemm_mma<0><<<gDD, 256, GEMM_SMEM>>>(ml, wout, out, h, D_MODEL, F_DIM);
}

// round 12
// speedup vs baseline: 2.6383x; 1.0264x over previous
#include <cuda_runtime.h>
#include <math.h>
#include <stdint.h>

#define D_MODEL 2048
#define F_DIM   8192
#define NROWS   4096   // B*S
#define NHEAD   16
#define HD      128
#define SEQ     2048

// ---------------- scratch (device globals; no allocations allowed) ----------
__device__ float g_xn [NROWS * D_MODEL];
__device__ float g_q  [NROWS * D_MODEL];
__device__ float g_k  [NROWS * D_MODEL];
__device__ float g_v  [NROWS * D_MODEL];
__device__ float g_ao [NROWS * D_MODEL];
__device__ float g_h  [NROWS * D_MODEL];
__device__ float g_ml [NROWS * F_DIM];

// ---------------- helpers ----------------------------------------------------
__device__ __forceinline__ float rna_tf32(float x) {
    float r;
    asm("cvt.rna.tf32.f32 %0, %1;" : "=f"(r) : "f"(x));
    return r;
}

__device__ __forceinline__ uint32_t smem_u32(const void* p) {
    uint32_t a;
    asm("{ .reg .u64 t; cvta.to.shared.u64 t, %1; cvt.u32.u64 %0, t; }" : "=r"(a) : "l"(p));
    return a;
}

#define CP_ASYNC16(dst, src) \
    asm volatile("cp.async.cg.shared.global [%0], [%1], 16;" :: "r"(dst), "l"(src) : "memory")
#define CP_COMMIT() asm volatile("cp.async.commit_group;" ::: "memory")
#define CP_WAIT(n)  asm volatile("cp.async.wait_group %0;" :: "n"(n) : "memory")

__device__ __forceinline__ void mma_tf32(float* c, const uint32_t* a, const uint32_t* b) {
    asm volatile(
        "mma.sync.aligned.m16n8k8.row.col.f32.tf32.tf32.f32 "
        "{%0,%1,%2,%3}, {%4,%5,%6,%7}, {%8,%9}, {%0,%1,%2,%3};"
        : "+f"(c[0]), "+f"(c[1]), "+f"(c[2]), "+f"(c[3])
        : "r"(a[0]), "r"(a[1]), "r"(a[2]), "r"(a[3]), "r"(b[0]), "r"(b[1]));
}

__device__ __forceinline__ float gelu_exact(float x) {
    return 0.5f * x * (1.0f + erff(x * 0.70710678118654752f));
}

// ---------------- hypersphere norm (output rounded to tf32) ------------------
__global__ void hnorm_kernel(const float* __restrict__ x,
                             const float* __restrict__ g,
                             float* __restrict__ out) {
    int row = blockIdx.x;
    int tid = threadIdx.x;
    const float4* xr = (const float4*)(x + (size_t)row * D_MODEL);
    float4 v0 = xr[tid];
    float4 v1 = xr[tid + 256];
    float ss = v0.x*v0.x + v0.y*v0.y + v0.z*v0.z + v0.w*v0.w
             + v1.x*v1.x + v1.y*v1.y + v1.z*v1.z + v1.w*v1.w;
    #pragma unroll
    for (int o = 16; o > 0; o >>= 1) ss += __shfl_xor_sync(0xffffffffu, ss, o);
    __shared__ float red[8];
    if ((tid & 31) == 0) red[tid >> 5] = ss;
    __syncthreads();
    float tot = red[0]+red[1]+red[2]+red[3]+red[4]+red[5]+red[6]+red[7];
    float scale = 45.254833995939045f / (sqrtf(tot) + 1e-6f);
    const float4* gg = (const float4*)g;
    float4 g0 = gg[tid], g1 = gg[tid + 256];
    float4* orow = (float4*)(out + (size_t)row * D_MODEL);
    float4 o0, o1;
    o0.x = rna_tf32(v0.x*scale*g0.x); o0.y = rna_tf32(v0.y*scale*g0.y);
    o0.z = rna_tf32(v0.z*scale*g0.z); o0.w = rna_tf32(v0.w*scale*g0.w);
    o1.x = rna_tf32(v1.x*scale*g1.x); o1.y = rna_tf32(v1.y*scale*g1.y);
    o1.z = rna_tf32(v1.z*scale*g1.z); o1.w = rna_tf32(v1.w*scale*g1.w);
    orow[tid] = o0;
    orow[tid + 256] = o1;
}

// ---------------- per-head QK norm -------------------------------------------
__global__ void qknorm_kernel(float* __restrict__ t, const float* __restrict__ fac) {
    int vec  = blockIdx.x * 8 + (threadIdx.x >> 5);
    int lane = threadIdx.x & 31;
    float4* p = (float4*)(t + (size_t)vec * HD);
    float4 v = p[lane];
    float ss = v.x*v.x + v.y*v.y + v.z*v.z + v.w*v.w;
    #pragma unroll
    for (int o = 16; o > 0; o >>= 1) ss += __shfl_xor_sync(0xffffffffu, ss, o);
    float f = fac ? fac[0] : 1.0f;
    float s = f / (sqrtf(ss) + 1e-6f);
    v.x *= s; v.y *= s; v.z *= s; v.w *= s;
    p[lane] = v;
}

// ---------------- tf32 mma.sync NT-GEMM: C[M,N]=A[M,K]*B[N,K]^T (+R, gelu) ---
// CTA tile 128x128, BK=32, 8 warps (2x4), warp tile 64x32, frags m16n8k8.
// 3-stage cp.async pipeline, ONE __syncthreads per K-iter, register
// double-buffered fragments. B (weight) fragments rounded to tf32 in-register
// (RNA); A operands are pre-rounded by their producer kernels.
// Smem tiles stored [row][36]: conflict-free fragment gathers, 144B row
// stride keeps cp.async 16B-aligned.
#define GKT     32
#define TSTR    36
#define NSTG    3
#define STG_FLT (2 * 128 * TSTR)                  // floats per stage (A+B)
#define GEMM_SMEM (NSTG * STG_FLT * 4)            // 110592 bytes

__device__ __forceinline__ void g_load_stage(uint32_t sbase, int s,
                                             const float* __restrict__ A,
                                             const float* __restrict__ B,
                                             int m0, int n0, int K, int j, int tid) {
    int k0 = j * GKT;
    uint32_t stage = sbase + (uint32_t)s * (STG_FLT * 4);
    #pragma unroll
    for (int t = 0; t < 4; t++) {
        int cid = tid + t * 256;          // 0..1023
        int r = cid >> 3, c = cid & 7;
        uint32_t dst = stage + (uint32_t)(r * TSTR + c * 4) * 4;
        CP_ASYNC16(dst, A + (size_t)(m0 + r) * K + k0 + c * 4);
    }
    #pragma unroll
    for (int t = 0; t < 4; t++) {
        int cid = tid + t * 256;
        int r = cid >> 3, c = cid & 7;
        uint32_t dst = stage + (uint32_t)(128 * TSTR + r * TSTR + c * 4) * 4;
        CP_ASYNC16(dst, B + (size_t)(n0 + r) * K + k0 + c * 4);
    }
}

__device__ __forceinline__ void g_load_frags(const float* __restrict__ As,
                                             const float* __restrict__ Bs,
                                             int warp_m, int warp_n,
                                             int qid, int qtr, int ks,
                                             uint32_t af[4][4], uint32_t bf[4][2]) {
    int k = ks * 8 + qtr;
    #pragma unroll
    for (int mi = 0; mi < 4; mi++) {
        const float* p = As + (warp_m * 64 + mi * 16 + qid) * TSTR + k;
        af[mi][0] = __float_as_uint(p[0]);
        af[mi][1] = __float_as_uint(p[8 * TSTR]);
        af[mi][2] = __float_as_uint(p[4]);
        af[mi][3] = __float_as_uint(p[8 * TSTR + 4]);
    }
    #pragma unroll
    for (int ni = 0; ni < 4; ni++) {
        const float* p = Bs + (warp_n * 32 + ni * 8 + qid) * TSTR + k;
        bf[ni][0] = __float_as_uint(rna_tf32(p[0]));
        bf[ni][1] = __float_as_uint(rna_tf32(p[4]));
    }
}

template<int EPI>   // 0 = none, 1 = GELU + round-to-tf32
__global__ __launch_bounds__(256)
void gemm_mma(const float* __restrict__ A, const float* __restrict__ B,
              float* __restrict__ C, const float* __restrict__ R,
              int N, int K) {
    extern __shared__ float smf[];
    uint32_t sbase = smem_u32(smf);

    int tid = threadIdx.x;
    int wid = tid >> 5, lane = tid & 31;
    int warp_m = wid >> 2, warp_n = wid & 3;     // 2 x 4 warp grid
    int m0 = blockIdx.y * 128, n0 = blockIdx.x * 128;
    int qid = lane >> 2, qtr = lane & 3;

    float acc[4][4][4];
    #pragma unroll
    for (int mi = 0; mi < 4; mi++)
        #pragma unroll
        for (int ni = 0; ni < 4; ni++)
            #pragma unroll
            for (int r = 0; r < 4; r++) acc[mi][ni][r] = 0.f;

    int KT = K / GKT;
    // prologue: 2 stages in flight
    g_load_stage(sbase, 0, A, B, m0, n0, K, 0, tid);
    CP_COMMIT();
    g_load_stage(sbase, 1, A, B, m0, n0, K, 1, tid);
    CP_COMMIT();

    int sidx = 0;                                 // = i % NSTG
    for (int i = 0; i < KT; i++) {
        CP_WAIT(1);                               // stage i resident
        __syncthreads();                          // also protects buf reuse (dist 3)

        const float* As = smf + sidx * STG_FLT;
        const float* Bs = As + 128 * TSTR;

        // issue load for stage i+2 (overlaps compute below)
        int s2 = sidx + 2; if (s2 >= NSTG) s2 -= NSTG;
        if (i + 2 < KT) g_load_stage(sbase, s2, A, B, m0, n0, K, i + 2, tid);
        CP_COMMIT();                              // uniform group accounting

        // compute stage i: 4 k-slices, register double-buffered fragments
        uint32_t af[2][4][4], bf[2][4][2];
        g_load_frags(As, Bs, warp_m, warp_n, qid, qtr, 0, af[0], bf[0]);
        #pragma unroll
        for (int ks = 0; ks < 4; ks++) {
            int cur = ks & 1, nxt = cur ^ 1;
            if (ks < 3)
                g_load_frags(As, Bs, warp_m, warp_n, qid, qtr, ks + 1, af[nxt], bf[nxt]);
            #pragma unroll
            for (int mi = 0; mi < 4; mi++)
                #pragma unroll
                for (int ni = 0; ni < 4; ni++)
                    mma_tf32(acc[mi][ni], af[cur][mi], bf[cur][ni]);
        }

        sidx++; if (sidx >= NSTG) sidx = 0;
    }

    // epilogue: c0/c1 at (row, 2q), c2/c3 at (row+8, 2q)
    #pragma unroll
    for (int mi = 0; mi < 4; mi++) {
        int r1 = m0 + warp_m * 64 + mi * 16 + qid;
        int r2 = r1 + 8;
        #pragma unroll
        for (int ni = 0; ni < 4; ni++) {
            int cc = n0 + warp_n * 32 + ni * 8 + 2 * qtr;
            float2 v0 = make_float2(acc[mi][ni][0], acc[mi][ni][1]);
            float2 v1 = make_float2(acc[mi][ni][2], acc[mi][ni][3]);
            if (R) {
                float2 rv0 = *(const float2*)(R + (size_t)r1 * N + cc);
                float2 rv1 = *(const float2*)(R + (size_t)r2 * N + cc);
                v0.x += rv0.x; v0.y += rv0.y;
                v1.x += rv1.x; v1.y += rv1.y;
            }
            if (EPI == 1) {
                v0.x = rna_tf32(gelu_exact(v0.x));
                v0.y = rna_tf32(gelu_exact(v0.y));
                v1.x = rna_tf32(gelu_exact(v1.x));
                v1.y = rna_tf32(gelu_exact(v1.y));
            }
            *(float2*)(C + (size_t)r1 * N + cc) = v0;
            *(float2*)(C + (size_t)r2 * N + cc) = v1;
        }
    }
}

// ---------------- causal flash attention (fp32, 64x64 tiles, hd=128) ---------
#define FB 64
#define KS_STRIDE 68

__global__ __launch_bounds__(256, 1)
void flash_kernel(const float* __restrict__ Q, const float* __restrict__ Kg,
                  const float* __restrict__ V, float* __restrict__ O) {
    extern __shared__ float smf[];
    float* Qs = smf;
    float* Ks = Qs + FB * HD;
    float* Vs = Ks + HD * KS_STRIDE;
    float* Ss = Vs + FB * HD;

    int qt = blockIdx.x, h = blockIdx.y, b = blockIdx.z;
    int tid = threadIdx.x;
    int w = tid >> 5, lane = tid & 31;
    int tx = tid & 15, ty = tid >> 4;
    size_t base = (size_t)b * SEQ * D_MODEL + (size_t)h * HD;
    int q0 = qt * FB;

    #pragma unroll
    for (int i = 0; i < 8; i++) {
        int f = tid + i * 256;
        int r = f >> 5;
        int d = (f & 31) << 2;
        *(float4*)&Qs[r * HD + d] =
            *(const float4*)(Q + base + (size_t)(q0 + r) * D_MODEL + d);
    }

    float m[8], l[8], oc[8][4];
    #pragma unroll
    for (int i = 0; i < 8; i++) {
        m[i] = -INFINITY; l[i] = 0.f;
        oc[i][0] = oc[i][1] = oc[i][2] = oc[i][3] = 0.f;
    }
    __syncthreads();

    for (int j0 = 0; j0 <= qt; j0++) {
        int k0 = j0 * FB;
        __syncthreads();
        #pragma unroll
        for (int i = 0; i < 8; i++) {
            int f = tid + i * 256;
            int r = f >> 5;
            int d = (f & 31) << 2;
            float4 kv = *(const float4*)(Kg + base + (size_t)(k0 + r) * D_MODEL + d);
            Ks[(d + 0) * KS_STRIDE + r] = kv.x;
            Ks[(d + 1) * KS_STRIDE + r] = kv.y;
            Ks[(d + 2) * KS_STRIDE + r] = kv.z;
            Ks[(d + 3) * KS_STRIDE + r] = kv.w;
            *(float4*)&Vs[r * HD + d] =
                *(const float4*)(V + base + (size_t)(k0 + r) * D_MODEL + d);
        }
        __syncthreads();

        float s[4][4];
        #pragma unroll
        for (int i = 0; i < 4; i++)
            #pragma unroll
            for (int j = 0; j < 4; j++) s[i][j] = 0.f;
        #pragma unroll 4
        for (int kk = 0; kk < HD; kk++) {
            float4 b4 = *(const float4*)&Ks[kk * KS_STRIDE + tx * 4];
            #pragma unroll
            for (int i = 0; i < 4; i++) {
                float a = Qs[(ty * 4 + i) * HD + kk];
                s[i][0] = fmaf(a, b4.x, s[i][0]);
                s[i][1] = fmaf(a, b4.y, s[i][1]);
                s[i][2] = fmaf(a, b4.z, s[i][2]);
                s[i][3] = fmaf(a, b4.w, s[i][3]);
            }
        }
        bool diag = (j0 == qt);
        #pragma unroll
        for (int i = 0; i < 4; i++)
            #pragma unroll
            for (int j = 0; j < 4; j++) {
                float v = s[i][j];
                if (diag && (tx * 4 + j) > (ty * 4 + i)) v = -1e30f;
                Ss[(ty * 4 + i) * FB + tx * 4 + j] = v;
            }
        __syncthreads();

        #pragma unroll
        for (int i = 0; i < 8; i++) {
            int r = w * 8 + i;
            float s0 = Ss[r * FB + lane];
            float s1 = Ss[r * FB + lane + 32];
            float mx = fmaxf(s0, s1);
            #pragma unroll
            for (int o = 16; o > 0; o >>= 1)
                mx = fmaxf(mx, __shfl_xor_sync(0xffffffffu, mx, o));
            float mnew = fmaxf(m[i], mx);
            float p0 = __expf(s0 - mnew);
            float p1 = __expf(s1 - mnew);
            Ss[r * FB + lane] = p0;
            Ss[r * FB + lane + 32] = p1;
            float ls = p0 + p1;
            #pragma unroll
            for (int o = 16; o > 0; o >>= 1)
                ls += __shfl_xor_sync(0xffffffffu, ls, o);
            float corr = __expf(m[i] - mnew);
            l[i] = l[i] * corr + ls;
            m[i] = mnew;
            oc[i][0] *= corr; oc[i][1] *= corr; oc[i][2] *= corr; oc[i][3] *= corr;
        }
        __syncwarp();

        for (int jj = 0; jj < FB; jj++) {
            float v0 = Vs[jj * HD + lane];
            float v1 = Vs[jj * HD + lane + 32];
            float v2 = Vs[jj * HD + lane + 64];
            float v3 = Vs[jj * HD + lane + 96];
            #pragma unroll
            for (int i = 0; i < 8; i++) {
                float p = Ss[(w * 8 + i) * FB + jj];
                oc[i][0] = fmaf(p, v0, oc[i][0]);
                oc[i][1] = fmaf(p, v1, oc[i][1]);
                oc[i][2] = fmaf(p, v2, oc[i][2]);
                oc[i][3] = fmaf(p, v3, oc[i][3]);
            }
        }
    }

    #pragma unroll
    for (int i = 0; i < 8; i++) {
        int r = w * 8 + i;
        float inv = 1.0f / l[i];
        float* orow = O + base + (size_t)(q0 + r) * D_MODEL;
        orow[lane]      = rna_tf32(oc[i][0] * inv);
        orow[lane + 32] = rna_tf32(oc[i][1] * inv);
        orow[lane + 64] = rna_tf32(oc[i][2] * inv);
        orow[lane + 96] = rna_tf32(oc[i][3] * inv);
    }
}

// ---------------- launch ------------------------------------------------------
extern "C" void kernel_launch(void* const* d_in, const int* in_sizes, int n_in,
                              void* d_out, int out_size) {
    const float* x     = (const float*)d_in[0];
    const float* Wq    = (const float*)d_in[1];
    const float* Wk    = (const float*)d_in[2];
    const float* Wv    = (const float*)d_in[3];
    const float* Wo    = (const float*)d_in[4];
    const float* W_in  = (const float*)d_in[5];
    const float* W_out = (const float*)d_in[6];
    const float* fac   = (const float*)d_in[7];
    const float* gatt  = (const float*)d_in[8];
    const float* gmlp  = (const float*)d_in[9];
    float* out = (float*)d_out;

    float *xn, *q, *k, *v, *ao, *h, *ml;
    cudaGetSymbolAddress((void**)&xn, g_xn);
    cudaGetSymbolAddress((void**)&q,  g_q);
    cudaGetSymbolAddress((void**)&k,  g_k);
    cudaGetSymbolAddress((void**)&v,  g_v);
    cudaGetSymbolAddress((void**)&ao, g_ao);
    cudaGetSymbolAddress((void**)&h,  g_h);
    cudaGetSymbolAddress((void**)&ml, g_ml);

    const int FLASH_SMEM = (FB*HD + HD*KS_STRIDE + FB*HD + FB*FB) * sizeof(float);
    cudaFuncSetAttribute(flash_kernel, cudaFuncAttributeMaxDynamicSharedMemorySize, FLASH_SMEM);
    cudaFuncSetAttribute(gemm_mma<0>, cudaFuncAttributeMaxDynamicSharedMemorySize, GEMM_SMEM);
    cudaFuncSetAttribute(gemm_mma<1>, cudaFuncAttributeMaxDynamicSharedMemorySize, GEMM_SMEM);

    // 1) pre-attention hypersphere norm (tf32-rounded output)
    hnorm_kernel<<<NROWS, 256>>>(x, gatt, xn);

    // 2) QKV projections (tensor-core tf32 mma.sync; weights rounded in-reg)
    dim3 gDD(D_MODEL / 128, NROWS / 128);
    gemm_mma<0><<<gDD, 256, GEMM_SMEM>>>(xn, Wq, q, nullptr, D_MODEL, D_MODEL);
    gemm_mma<0><<<gDD, 256, GEMM_SMEM>>>(xn, Wk, k, nullptr, D_MODEL, D_MODEL);
    gemm_mma<0><<<gDD, 256, GEMM_SMEM>>>(xn, Wv, v, nullptr, D_MODEL, D_MODEL);

    // 3) QK norm (factor folded into q)
    qknorm_kernel<<<NROWS * NHEAD / 8, 256>>>(q, fac);
    qknorm_kernel<<<NROWS * NHEAD / 8, 256>>>(k, nullptr);

    // 4) causal flash attention (fp32; output rounded to tf32 for Wo GEMM)
    flash_kernel<<<dim3(SEQ/FB, NHEAD, 2), 256, FLASH_SMEM>>>(q, k, v, ao);

    // 5) output projection + residual
    gemm_mma<0><<<gDD, 256, GEMM_SMEM>>>(ao, Wo, h, x, D_MODEL, D_MODEL);

    // 6) pre-MLP hypersphere norm
    hnorm_kernel<<<NROWS, 256>>>(h, gmlp, xn);

    // 7) MLP in + GELU (+ tf32 round for next GEMM's A)
    gemm_mma<1><<<dim3(F_DIM / 128, NROWS / 128), 256, GEMM_SMEM>>>(xn, W_in, ml, nullptr, F_DIM, D_MODEL);

    // 8) MLP out + residual -> final
    gemm_mma<0><<<gDD, 256, GEMM_SMEM>>>(ml, W_out, out, h, D_MODEL, F_DIM);
}

// round 17
// speedup vs baseline: 2.6824x; 1.0167x over previous
#include <cuda_runtime.h>
#include <math.h>
#include <stdint.h>

#define D_MODEL 2048
#define F_DIM   8192
#define NROWS   4096   // B*S
#define NHEAD   16
#define HD      128
#define SEQ     2048

// ---------------- scratch (device globals; no allocations allowed) ----------
__device__ float g_xn [NROWS * D_MODEL];
__device__ float g_q  [NROWS * D_MODEL];
__device__ float g_k  [NROWS * D_MODEL];
__device__ float g_v  [NROWS * D_MODEL];
__device__ float g_ao [NROWS * D_MODEL];
__device__ float g_h  [NROWS * D_MODEL];
__device__ float g_ml [NROWS * F_DIM];
// tf32-rounded weights (one-time per call)
__device__ float g_wq  [D_MODEL * D_MODEL];
__device__ float g_wk  [D_MODEL * D_MODEL];
__device__ float g_wv  [D_MODEL * D_MODEL];
__device__ float g_wo  [D_MODEL * D_MODEL];
__device__ float g_win [F_DIM * D_MODEL];
__device__ float g_wout[D_MODEL * F_DIM];

// ---------------- helpers ----------------------------------------------------
__device__ __forceinline__ float rna_tf32(float x) {
    float r;
    asm("cvt.rna.tf32.f32 %0, %1;" : "=f"(r) : "f"(x));
    return r;
}

__device__ __forceinline__ uint32_t smem_u32(const void* p) {
    uint32_t a;
    asm("{ .reg .u64 t; cvta.to.shared.u64 t, %1; cvt.u32.u64 %0, t; }" : "=r"(a) : "l"(p));
    return a;
}

#define CP_ASYNC16(dst, src) \
    asm volatile("cp.async.cg.shared.global [%0], [%1], 16;" :: "r"(dst), "l"(src) : "memory")
#define CP_COMMIT() asm volatile("cp.async.commit_group;" ::: "memory")
#define CP_WAIT(n)  asm volatile("cp.async.wait_group %0;" :: "n"(n) : "memory")

__device__ __forceinline__ void mma_tf32(float* c, const uint32_t* a, const uint32_t* b) {
    asm volatile(
        "mma.sync.aligned.m16n8k8.row.col.f32.tf32.tf32.f32 "
        "{%0,%1,%2,%3}, {%4,%5,%6,%7}, {%8,%9}, {%0,%1,%2,%3};"
        : "+f"(c[0]), "+f"(c[1]), "+f"(c[2]), "+f"(c[3])
        : "r"(a[0]), "r"(a[1]), "r"(a[2]), "r"(a[3]), "r"(b[0]), "r"(b[1]));
}

__device__ __forceinline__ float gelu_exact(float x) {
    return 0.5f * x * (1.0f + erff(x * 0.70710678118654752f));
}

// ---------------- weight rounding to tf32 (RNA, one-time) --------------------
__global__ void round4_kernel(const float4* __restrict__ in, float4* __restrict__ out, int n4) {
    int i = blockIdx.x * blockDim.x + threadIdx.x;
    if (i < n4) {
        float4 v = in[i];
        v.x = rna_tf32(v.x); v.y = rna_tf32(v.y);
        v.z = rna_tf32(v.z); v.w = rna_tf32(v.w);
        out[i] = v;
    }
}

// ---------------- hypersphere norm (output rounded to tf32) ------------------
__global__ void hnorm_kernel(const float* __restrict__ x,
                             const float* __restrict__ g,
                             float* __restrict__ out) {
    int row = blockIdx.x;
    int tid = threadIdx.x;
    const float4* xr = (const float4*)(x + (size_t)row * D_MODEL);
    float4 v0 = xr[tid];
    float4 v1 = xr[tid + 256];
    float ss = v0.x*v0.x + v0.y*v0.y + v0.z*v0.z + v0.w*v0.w
             + v1.x*v1.x + v1.y*v1.y + v1.z*v1.z + v1.w*v1.w;
    #pragma unroll
    for (int o = 16; o > 0; o >>= 1) ss += __shfl_xor_sync(0xffffffffu, ss, o);
    __shared__ float red[8];
    if ((tid & 31) == 0) red[tid >> 5] = ss;
    __syncthreads();
    float tot = red[0]+red[1]+red[2]+red[3]+red[4]+red[5]+red[6]+red[7];
    float scale = 45.254833995939045f / (sqrtf(tot) + 1e-6f);
    const float4* gg = (const float4*)g;
    float4 g0 = gg[tid], g1 = gg[tid + 256];
    float4* orow = (float4*)(out + (size_t)row * D_MODEL);
    float4 o0, o1;
    o0.x = rna_tf32(v0.x*scale*g0.x); o0.y = rna_tf32(v0.y*scale*g0.y);
    o0.z = rna_tf32(v0.z*scale*g0.z); o0.w = rna_tf32(v0.w*scale*g0.w);
    o1.x = rna_tf32(v1.x*scale*g1.x); o1.y = rna_tf32(v1.y*scale*g1.y);
    o1.z = rna_tf32(v1.z*scale*g1.z); o1.w = rna_tf32(v1.w*scale*g1.w);
    orow[tid] = o0;
    orow[tid + 256] = o1;
}

// ---------------- per-head QK norm -------------------------------------------
__global__ void qknorm_kernel(float* __restrict__ t, const float* __restrict__ fac) {
    int vec  = blockIdx.x * 8 + (threadIdx.x >> 5);
    int lane = threadIdx.x & 31;
    float4* p = (float4*)(t + (size_t)vec * HD);
    float4 v = p[lane];
    float ss = v.x*v.x + v.y*v.y + v.z*v.z + v.w*v.w;
    #pragma unroll
    for (int o = 16; o > 0; o >>= 1) ss += __shfl_xor_sync(0xffffffffu, ss, o);
    float f = fac ? fac[0] : 1.0f;
    float s = f / (sqrtf(ss) + 1e-6f);
    v.x *= s; v.y *= s; v.z *= s; v.w *= s;
    p[lane] = v;
}

// ---------------- tf32 mma.sync NT-GEMM: C[M,N]=A[M,K]*B[N,K]^T (+R, gelu) ---
// CTA tile 128x128, BK=32, 8 warps (2x4), warp tile 64x32, frags m16n8k8.
// 3-stage cp.async pipeline, ONE __syncthreads per K-iter, register
// double-buffered fragments. XOR-swizzled smem (no padding):
//   float index = row*32 + ((k & ~3) ^ ((row & 7) << 2)) + (k & 3)
// -> conflict-free fragment gathers AND 16B-granular cp.async writes,
//    stage = 32KB (A+B), 3 stages = 96KB/CTA -> 2 CTAs/SM.
#define GKT     32
#define NSTG    3
#define STG_FLT (2 * 128 * 32)                    // floats per stage (A+B)
#define GEMM_SMEM (NSTG * STG_FLT * 4)            // 98304 bytes

__device__ __forceinline__ uint32_t sw_off(int row, int k4) {
    // k4 = k & ~3 (16B chunk index*4); returns float offset of chunk start
    return (uint32_t)(row * 32 + (k4 ^ ((row & 7) << 2)));
}

__device__ __forceinline__ void g_load_stage(uint32_t sbase, int s,
                                             const float* __restrict__ A,
                                             const float* __restrict__ B,
                                             int m0, int n0, int K, int j, int tid) {
    int k0 = j * GKT;
    uint32_t stage = sbase + (uint32_t)s * (STG_FLT * 4);
    #pragma unroll
    for (int t = 0; t < 4; t++) {
        int cid = tid + t * 256;          // 0..1023
        int r = cid >> 3, c = cid & 7;
        uint32_t dst = stage + sw_off(r, c * 4) * 4;
        CP_ASYNC16(dst, A + (size_t)(m0 + r) * K + k0 + c * 4);
    }
    #pragma unroll
    for (int t = 0; t < 4; t++) {
        int cid = tid + t * 256;
        int r = cid >> 3, c = cid & 7;
        uint32_t dst = stage + (uint32_t)(128 * 32 + sw_off(r, c * 4)) * 4;
        CP_ASYNC16(dst, B + (size_t)(n0 + r) * K + k0 + c * 4);
    }
}

__device__ __forceinline__ void g_load_frags(const float* __restrict__ As,
                                             const float* __restrict__ Bs,
                                             int warp_m, int warp_n,
                                             int qid, int qtr, int ks,
                                             uint32_t af[4][4], uint32_t bf[4][2]) {
    int kb = ks * 8;                      // k-slice base (k = kb + qtr / +4)
    #pragma unroll
    for (int mi = 0; mi < 4; mi++) {
        int r = warp_m * 64 + mi * 16 + qid;
        const float* p0 = As + sw_off(r,     kb)     + qtr;
        const float* p1 = As + sw_off(r + 8, kb)     + qtr;
        const float* p2 = As + sw_off(r,     kb + 4) + qtr;
        const float* p3 = As + sw_off(r + 8, kb + 4) + qtr;
        af[mi][0] = __float_as_uint(*p0);
        af[mi][1] = __float_as_uint(*p1);
        af[mi][2] = __float_as_uint(*p2);
        af[mi][3] = __float_as_uint(*p3);
    }
    #pragma unroll
    for (int ni = 0; ni < 4; ni++) {
        int r = warp_n * 32 + ni * 8 + qid;
        bf[ni][0] = __float_as_uint(*(Bs + sw_off(r, kb)     + qtr));
        bf[ni][1] = __float_as_uint(*(Bs + sw_off(r, kb + 4) + qtr));
    }
}

template<int EPI>   // 0 = none, 1 = GELU + round-to-tf32
__global__ __launch_bounds__(256, 2)
void gemm_mma(const float* __restrict__ A, const float* __restrict__ B,
              float* __restrict__ C, const float* __restrict__ R,
              int N, int K) {
    extern __shared__ float smf[];
    uint32_t sbase = smem_u32(smf);

    int tid = threadIdx.x;
    int wid = tid >> 5, lane = tid & 31;
    int warp_m = wid >> 2, warp_n = wid & 3;     // 2 x 4 warp grid
    int m0 = blockIdx.y * 128, n0 = blockIdx.x * 128;
    int qid = lane >> 2, qtr = lane & 3;

    float acc[4][4][4];
    #pragma unroll
    for (int mi = 0; mi < 4; mi++)
        #pragma unroll
        for (int ni = 0; ni < 4; ni++)
            #pragma unroll
            for (int r = 0; r < 4; r++) acc[mi][ni][r] = 0.f;

    int KT = K / GKT;
    // prologue: 2 stages in flight
    g_load_stage(sbase, 0, A, B, m0, n0, K, 0, tid);
    CP_COMMIT();
    g_load_stage(sbase, 1, A, B, m0, n0, K, 1, tid);
    CP_COMMIT();

    int sidx = 0;                                 // = i % NSTG
    for (int i = 0; i < KT; i++) {
        CP_WAIT(1);                               // stage i resident
        __syncthreads();                          // also protects buf reuse (dist 3)

        const float* As = smf + sidx * STG_FLT;
        const float* Bs = As + 128 * 32;

        // issue load for stage i+2 (overlaps compute below)
        int s2 = sidx + 2; if (s2 >= NSTG) s2 -= NSTG;
        if (i + 2 < KT) g_load_stage(sbase, s2, A, B, m0, n0, K, i + 2, tid);
        CP_COMMIT();                              // uniform group accounting

        // compute stage i: 4 k-slices, register double-buffered fragments
        uint32_t af[2][4][4], bf[2][4][2];
        g_load_frags(As, Bs, warp_m, warp_n, qid, qtr, 0, af[0], bf[0]);
        #pragma unroll
        for (int ks = 0; ks < 4; ks++) {
            int cur = ks & 1, nxt = cur ^ 1;
            if (ks < 3)
                g_load_frags(As, Bs, warp_m, warp_n, qid, qtr, ks + 1, af[nxt], bf[nxt]);
            #pragma unroll
            for (int mi = 0; mi < 4; mi++)
                #pragma unroll
                for (int ni = 0; ni < 4; ni++)
                    mma_tf32(acc[mi][ni], af[cur][mi], bf[cur][ni]);
        }

        sidx++; if (sidx >= NSTG) sidx = 0;
    }

    // epilogue: c0/c1 at (row, 2q), c2/c3 at (row+8, 2q)
    #pragma unroll
    for (int mi = 0; mi < 4; mi++) {
        int r1 = m0 + warp_m * 64 + mi * 16 + qid;
        int r2 = r1 + 8;
        #pragma unroll
        for (int ni = 0; ni < 4; ni++) {
            int cc = n0 + warp_n * 32 + ni * 8 + 2 * qtr;
            float2 v0 = make_float2(acc[mi][ni][0], acc[mi][ni][1]);
            float2 v1 = make_float2(acc[mi][ni][2], acc[mi][ni][3]);
            if (R) {
                float2 rv0 = *(const float2*)(R + (size_t)r1 * N + cc);
                float2 rv1 = *(const float2*)(R + (size_t)r2 * N + cc);
                v0.x += rv0.x; v0.y += rv0.y;
                v1.x += rv1.x; v1.y += rv1.y;
            }
            if (EPI == 1) {
                v0.x = rna_tf32(gelu_exact(v0.x));
                v0.y = rna_tf32(gelu_exact(v0.y));
                v1.x = rna_tf32(gelu_exact(v1.x));
                v1.y = rna_tf32(gelu_exact(v1.y));
            }
            *(float2*)(C + (size_t)r1 * N + cc) = v0;
            *(float2*)(C + (size_t)r2 * N + cc) = v1;
        }
    }
}

// ---------------- causal flash attention (fp32, 64x64 tiles, hd=128) ---------
#define FB 64
#define KS_STRIDE 68

__global__ __launch_bounds__(256, 1)
void flash_kernel(const float* __restrict__ Q, const float* __restrict__ Kg,
                  const float* __restrict__ V, float* __restrict__ O) {
    extern __shared__ float smf[];
    float* Qs = smf;
    float* Ks = Qs + FB * HD;
    float* Vs = Ks + HD * KS_STRIDE;
    float* Ss = Vs + FB * HD;

    int qt = blockIdx.x, h = blockIdx.y, b = blockIdx.z;
    int tid = threadIdx.x;
    int w = tid >> 5, lane = tid & 31;
    int tx = tid & 15, ty = tid >> 4;
    size_t base = (size_t)b * SEQ * D_MODEL + (size_t)h * HD;
    int q0 = qt * FB;

    #pragma unroll
    for (int i = 0; i < 8; i++) {
        int f = tid + i * 256;
        int r = f >> 5;
        int d = (f & 31) << 2;
        *(float4*)&Qs[r * HD + d] =
            *(const float4*)(Q + base + (size_t)(q0 + r) * D_MODEL + d);
    }

    float m[8], l[8], oc[8][4];
    #pragma unroll
    for (int i = 0; i < 8; i++) {
        m[i] = -INFINITY; l[i] = 0.f;
        oc[i][0] = oc[i][1] = oc[i][2] = oc[i][3] = 0.f;
    }
    __syncthreads();

    for (int j0 = 0; j0 <= qt; j0++) {
        int k0 = j0 * FB;
        __syncthreads();
        #pragma unroll
        for (int i = 0; i < 8; i++) {
            int f = tid + i * 256;
            int r = f >> 5;
            int d = (f & 31) << 2;
            float4 kv = *(const float4*)(Kg + base + (size_t)(k0 + r) * D_MODEL + d);
            Ks[(d + 0) * KS_STRIDE + r] = kv.x;
            Ks[(d + 1) * KS_STRIDE + r] = kv.y;
            Ks[(d + 2) * KS_STRIDE + r] = kv.z;
            Ks[(d + 3) * KS_STRIDE + r] = kv.w;
            *(float4*)&Vs[r * HD + d] =
                *(const float4*)(V + base + (size_t)(k0 + r) * D_MODEL + d);
        }
        __syncthreads();

        float s[4][4];
        #pragma unroll
        for (int i = 0; i < 4; i++)
            #pragma unroll
            for (int j = 0; j < 4; j++) s[i][j] = 0.f;
        #pragma unroll 4
        for (int kk = 0; kk < HD; kk++) {
            float4 b4 = *(const float4*)&Ks[kk * KS_STRIDE + tx * 4];
            #pragma unroll
            for (int i = 0; i < 4; i++) {
                float a = Qs[(ty * 4 + i) * HD + kk];
                s[i][0] = fmaf(a, b4.x, s[i][0]);
                s[i][1] = fmaf(a, b4.y, s[i][1]);
                s[i][2] = fmaf(a, b4.z, s[i][2]);
                s[i][3] = fmaf(a, b4.w, s[i][3]);
            }
        }
        bool diag = (j0 == qt);
        #pragma unroll
        for (int i = 0; i < 4; i++)
            #pragma unroll
            for (int j = 0; j < 4; j++) {
                float v = s[i][j];
                if (diag && (tx * 4 + j) > (ty * 4 + i)) v = -1e30f;
                Ss[(ty * 4 + i) * FB + tx * 4 + j] = v;
            }
        __syncthreads();

        #pragma unroll
        for (int i = 0; i < 8; i++) {
            int r = w * 8 + i;
            float s0 = Ss[r * FB + lane];
            float s1 = Ss[r * FB + lane + 32];
            float mx = fmaxf(s0, s1);
            #pragma unroll
            for (int o = 16; o > 0; o >>= 1)
                mx = fmaxf(mx, __shfl_xor_sync(0xffffffffu, mx, o));
            float mnew = fmaxf(m[i], mx);
            float p0 = __expf(s0 - mnew);
            float p1 = __expf(s1 - mnew);
            Ss[r * FB + lane] = p0;
            Ss[r * FB + lane + 32] = p1;
            float ls = p0 + p1;
            #pragma unroll
            for (int o = 16; o > 0; o >>= 1)
                ls += __shfl_xor_sync(0xffffffffu, ls, o);
            float corr = __expf(m[i] - mnew);
            l[i] = l[i] * corr + ls;
            m[i] = mnew;
            oc[i][0] *= corr; oc[i][1] *= corr; oc[i][2] *= corr; oc[i][3] *= corr;
        }
        __syncwarp();

        for (int jj = 0; jj < FB; jj++) {
            float v0 = Vs[jj * HD + lane];
            float v1 = Vs[jj * HD + lane + 32];
            float v2 = Vs[jj * HD + lane + 64];
            float v3 = Vs[jj * HD + lane + 96];
            #pragma unroll
            for (int i = 0; i < 8; i++) {
                float p = Ss[(w * 8 + i) * FB + jj];
                oc[i][0] = fmaf(p, v0, oc[i][0]);
                oc[i][1] = fmaf(p, v1, oc[i][1]);
                oc[i][2] = fmaf(p, v2, oc[i][2]);
                oc[i][3] = fmaf(p, v3, oc[i][3]);
            }
        }
    }

    #pragma unroll
    for (int i = 0; i < 8; i++) {
        int r = w * 8 + i;
        float inv = 1.0f / l[i];
        float* orow = O + base + (size_t)(q0 + r) * D_MODEL;
        orow[lane]      = rna_tf32(oc[i][0] * inv);
        orow[lane + 32] = rna_tf32(oc[i][1] * inv);
        orow[lane + 64] = rna_tf32(oc[i][2] * inv);
        orow[lane + 96] = rna_tf32(oc[i][3] * inv);
    }
}

// ---------------- launch ------------------------------------------------------
extern "C" void kernel_launch(void* const* d_in, const int* in_sizes, int n_in,
                              void* d_out, int out_size) {
    const float* x     = (const float*)d_in[0];
    const float* Wq    = (const float*)d_in[1];
    const float* Wk    = (const float*)d_in[2];
    const float* Wv    = (const float*)d_in[3];
    const float* Wo    = (const float*)d_in[4];
    const float* W_in  = (const float*)d_in[5];
    const float* W_out = (const float*)d_in[6];
    const float* fac   = (const float*)d_in[7];
    const float* gatt  = (const float*)d_in[8];
    const float* gmlp  = (const float*)d_in[9];
    float* out = (float*)d_out;

    float *xn, *q, *k, *v, *ao, *h, *ml;
    float *wq, *wk, *wv, *wo, *win, *wout;
    cudaGetSymbolAddress((void**)&xn, g_xn);
    cudaGetSymbolAddress((void**)&q,  g_q);
    cudaGetSymbolAddress((void**)&k,  g_k);
    cudaGetSymbolAddress((void**)&v,  g_v);
    cudaGetSymbolAddress((void**)&ao, g_ao);
    cudaGetSymbolAddress((void**)&h,  g_h);
    cudaGetSymbolAddress((void**)&ml, g_ml);
    cudaGetSymbolAddress((void**)&wq, g_wq);
    cudaGetSymbolAddress((void**)&wk, g_wk);
    cudaGetSymbolAddress((void**)&wv, g_wv);
    cudaGetSymbolAddress((void**)&wo, g_wo);
    cudaGetSymbolAddress((void**)&win,  g_win);
    cudaGetSymbolAddress((void**)&wout, g_wout);

    const int FLASH_SMEM = (FB*HD + HD*KS_STRIDE + FB*HD + FB*FB) * sizeof(float);
    cudaFuncSetAttribute(flash_kernel, cudaFuncAttributeMaxDynamicSharedMemorySize, FLASH_SMEM);
    cudaFuncSetAttribute(gemm_mma<0>, cudaFuncAttributeMaxDynamicSharedMemorySize, GEMM_SMEM);
    cudaFuncSetAttribute(gemm_mma<1>, cudaFuncAttributeMaxDynamicSharedMemorySize, GEMM_SMEM);

    // 0) round weights to tf32 (RNA) once per call — removes cvt from GEMM loop
    const int nDD = D_MODEL * D_MODEL / 4;
    const int nFD = F_DIM * D_MODEL / 4;
    round4_kernel<<<(nDD + 255) / 256, 256>>>((const float4*)Wq, (float4*)wq, nDD);
    round4_kernel<<<(nDD + 255) / 256, 256>>>((const float4*)Wk, (float4*)wk, nDD);
    round4_kernel<<<(nDD + 255) / 256, 256>>>((const float4*)Wv, (float4*)wv, nDD);
    round4_kernel<<<(nFD + 255) / 256, 256>>>((const float4*)W_in,  (float4*)win,  nFD);
    round4_kernel<<<(nFD + 255) / 256, 256>>>((const float4*)W_out, (float4*)wout, nFD);
    round4_kernel<<<(nDD + 255) / 256, 256>>>((const float4*)Wo, (float4*)wo, nDD);

    // 1) pre-attention hypersphere norm (tf32-rounded output)
    hnorm_kernel<<<NROWS, 256>>>(x, gatt, xn);

    // 2) QKV projections (tensor-core tf32 mma.sync)
    dim3 gDD(D_MODEL / 128, NROWS / 128);
    gemm_mma<0><<<gDD, 256, GEMM_SMEM>>>(xn, wq, q, nullptr, D_MODEL, D_MODEL);
    gemm_mma<0><<<gDD, 256, GEMM_SMEM>>>(xn, wk, k, nullptr, D_MODEL, D_MODEL);
    gemm_mma<0><<<gDD, 256, GEMM_SMEM>>>(xn, wv, v, nullptr, D_MODEL, D_MODEL);

    // 3) QK norm (factor folded into q)
    qknorm_kernel<<<NROWS * NHEAD / 8, 256>>>(q, fac);
    qknorm_kernel<<<NROWS * NHEAD / 8, 256>>>(k, nullptr);

    // 4) causal flash attention (fp32; output rounded to tf32 for Wo GEMM)
    flash_kernel<<<dim3(SEQ/FB, NHEAD, 2), 256, FLASH_SMEM>>>(q, k, v, ao);

    // 5) output projection + residual
    gemm_mma<0><<<gDD, 256, GEMM_SMEM>>>(ao, wo, h, x, D_MODEL, D_MODEL);

    // 6) pre-MLP hypersphere norm
    hnorm_kernel<<<NROWS, 256>>>(h, gmlp, xn);

    // 7) MLP in + GELU (+ tf32 round for next GEMM's A)
    gemm_mma<1><<<dim3(F_DIM / 128, NROWS / 128), 256, GEMM_SMEM>>>(xn, win, ml, nullptr, F_DIM, D_MODEL);

    // 8) MLP out + residual -> final
    gemm_mma<0><<<gDD, 256, GEMM_SMEM>>>(ml, wout, out, h, D_MODEL, F_DIM);
}